// round 2
// baseline (speedup 1.0000x reference)
#include <cuda_runtime.h>
#include <math.h>

#define NB    1024
#define EMB   400
#define WW    20
#define FHW   18
#define FSZ   324
#define RN    96
#define RELF  864
#define NSET  6
#define EPSf  1e-5f

// ---------------- scratch (static device globals; no runtime allocation) ----
__device__ float d_rhat[(size_t)NB * RELF];          // BN'd gathered relation rows [b][864]
__device__ float d_part[NSET * NB * 2];              // per-(set,b) sum/sumsq of E row
__device__ float d_PQ[(size_t)NSET * NB * 54];       // per-(set,b): P[9], Q[45] (raw image)
__device__ float d_ab[NSET * 2];                     // per-set BN0 alpha, beta
__device__ float d_ss[NSET * RN * 2];                // per-(set,r) BN1 scale, shift
__device__ float d_soft[(size_t)NSET * NB * FSZ];    // per-set softmax outputs

struct EPtrs { const int* e[NSET]; };

// ---------------- deterministic reductions ----------------------------------
__device__ __forceinline__ float warp_sum(float v) {
#pragma unroll
    for (int o = 16; o > 0; o >>= 1) v += __shfl_down_sync(0xffffffffu, v, o);
    return v;
}
__device__ __forceinline__ float warp_max(float v) {
#pragma unroll
    for (int o = 16; o > 0; o >>= 1) v = fmaxf(v, __shfl_down_sync(0xffffffffu, v, o));
    return v;
}

// ---------------- kernel 1: BN of gathered relation rows --------------------
// grid = 864 (one feature per block), 256 threads; 4 samples per thread.
__global__ void krel(const int* __restrict__ r_idx, const float* __restrict__ R,
                     const float* __restrict__ g2, const float* __restrict__ b2) {
    int f = blockIdx.x;
    int t = threadIdx.x;
    float v[4], s = 0.f, s2 = 0.f;
#pragma unroll
    for (int i = 0; i < 4; i++) {
        int b = t + i * 256;
        v[i] = R[(size_t)r_idx[b] * RELF + f];
        s += v[i];
        s2 += v[i] * v[i];
    }
    __shared__ float sh[8][2];
    float ws = warp_sum(s), ws2 = warp_sum(s2);
    int wid = t >> 5, lane = t & 31;
    if (lane == 0) { sh[wid][0] = ws; sh[wid][1] = ws2; }
    __syncthreads();
    __shared__ float sc_s, sf_s;
    if (t == 0) {
        float S = 0.f, S2 = 0.f;
#pragma unroll
        for (int w = 0; w < 8; w++) { S += sh[w][0]; S2 += sh[w][1]; }
        float m   = S * (1.f / NB);
        float var = S2 * (1.f / NB) - m * m;
        float sc  = rsqrtf(var + EPSf) * g2[f];
        sc_s = sc;
        sf_s = b2[f] - m * sc;
    }
    __syncthreads();
    float sc = sc_s, sf = sf_s;
#pragma unroll
    for (int i = 0; i < 4; i++) {
        int b = t + i * 256;
        d_rhat[(size_t)b * RELF + f] = fmaf(v[i], sc, sf);
    }
}

// ---------------- kernel 2: per-sample E-row stats + raw patch P/Q ----------
// grid = (1024, 6), 128 threads per block.
__global__ void kstats1(EPtrs ep, const float* __restrict__ E) {
    int set = blockIdx.y, b = blockIdx.x, t = threadIdx.x;
    int eid = ep.e[set][b];
    __shared__ float img[EMB];
    float s = 0.f, s2 = 0.f;
    for (int i = t; i < EMB; i += 128) {
        float v = E[(size_t)eid * EMB + i];
        img[i] = v;
        s += v;
        s2 += v * v;
    }
    float ws = warp_sum(s), ws2 = warp_sum(s2);
    __shared__ float shp[4][2];
    int wid = t >> 5, lane = t & 31;
    if (lane == 0) { shp[wid][0] = ws; shp[wid][1] = ws2; }
    __syncthreads();   // also makes img visible to everyone
    if (t == 0) {
        d_part[(set * NB + b) * 2 + 0] = shp[0][0] + shp[1][0] + shp[2][0] + shp[3][0];
        d_part[(set * NB + b) * 2 + 1] = shp[0][1] + shp[1][1] + shp[2][1] + shp[3][1];
    }

    float aP[9], aQ[45];
#pragma unroll
    for (int i = 0; i < 9; i++)  aP[i] = 0.f;
#pragma unroll
    for (int i = 0; i < 45; i++) aQ[i] = 0.f;

    for (int pos = t; pos < FSZ; pos += 128) {
        int y = pos / FHW, x = pos - y * FHW;
        float p[9];
#pragma unroll
        for (int dy = 0; dy < 3; dy++)
#pragma unroll
            for (int dx = 0; dx < 3; dx++)
                p[dy * 3 + dx] = img[(y + dy) * WW + (x + dx)];
        int q = 0;
#pragma unroll
        for (int k1 = 0; k1 < 9; k1++) {
            aP[k1] += p[k1];
#pragma unroll
            for (int k2 = k1; k2 < 9; k2++) { aQ[q] += p[k1] * p[k2]; q++; }
        }
    }
#pragma unroll
    for (int c = 0; c < 9; c++)  aP[c] = warp_sum(aP[c]);
#pragma unroll
    for (int c = 0; c < 45; c++) aQ[c] = warp_sum(aQ[c]);

    __shared__ float sred[4][54];
    if (lane == 0) {
#pragma unroll
        for (int c = 0; c < 9; c++)  sred[wid][c] = aP[c];
#pragma unroll
        for (int c = 0; c < 45; c++) sred[wid][9 + c] = aQ[c];
    }
    __syncthreads();
    if (t < 54) {
        float v = sred[0][t] + sred[1][t] + sred[2][t] + sred[3][t];
        d_PQ[((size_t)set * NB + b) * 54 + t] = v;
    }
}

// ---------------- kernel 3: BN0 scalar stats -> alpha/beta ------------------
// grid = 6, 256 threads.
__global__ void kreduce0(const float* __restrict__ g0, const float* __restrict__ b0) {
    int set = blockIdx.x, t = threadIdx.x;
    float s = 0.f, s2 = 0.f;
    for (int b = t; b < NB; b += 256) {
        s  += d_part[(set * NB + b) * 2 + 0];
        s2 += d_part[(set * NB + b) * 2 + 1];
    }
    float ws = warp_sum(s), ws2 = warp_sum(s2);
    __shared__ float sh[8][2];
    int wid = t >> 5, lane = t & 31;
    if (lane == 0) { sh[wid][0] = ws; sh[wid][1] = ws2; }
    __syncthreads();
    if (t == 0) {
        float S = 0.f, S2 = 0.f;
#pragma unroll
        for (int w = 0; w < 8; w++) { S += sh[w][0]; S2 += sh[w][1]; }
        const float inv = 1.f / ((float)NB * EMB);
        float m   = S * inv;
        float var = S2 * inv - m * m;
        float a   = g0[0] * rsqrtf(var + EPSf);
        d_ab[set * 2 + 0] = a;
        d_ab[set * 2 + 1] = b0[0] - m * a;
    }
}

// ---------------- kernel 4: BN1 per-channel stats via P/Q -------------------
// grid = (96, 6), 256 threads.
__global__ void kstats2(const float* __restrict__ g1, const float* __restrict__ b1) {
    int r = blockIdx.x, set = blockIdx.y, t = threadIdx.x;
    float alpha = d_ab[set * 2 + 0], beta = d_ab[set * 2 + 1];
    float S1 = 0.f, S2 = 0.f;
    for (int b = t; b < NB; b += 256) {
        const float* pq = &d_PQ[((size_t)set * NB + b) * 54];
        const float* rh = &d_rhat[(size_t)b * RELF + r * 9];
        float rhv[9], Srh = 0.f, SrP = 0.f;
#pragma unroll
        for (int k = 0; k < 9; k++) {
            rhv[k] = rh[k];
            Srh += rhv[k];
            SrP += rhv[k] * pq[k];
        }
        float quad = 0.f;
        int q = 0;
#pragma unroll
        for (int k1 = 0; k1 < 9; k1++) {
            quad += rhv[k1] * rhv[k1] * pq[9 + q]; q++;
#pragma unroll
            for (int k2 = k1 + 1; k2 < 9; k2++) {
                quad += 2.f * rhv[k1] * rhv[k2] * pq[9 + q]; q++;
            }
        }
        float mC = alpha * SrP + (float)FSZ * beta * Srh;
        float x2 = alpha * alpha * quad
                 + 2.f * alpha * beta * Srh * SrP
                 + (float)FSZ * beta * beta * Srh * Srh;
        S1 += mC;
        S2 += x2;
    }
    float w1 = warp_sum(S1), w2 = warp_sum(S2);
    __shared__ float sh[8][2];
    int wid = t >> 5, lane = t & 31;
    if (lane == 0) { sh[wid][0] = w1; sh[wid][1] = w2; }
    __syncthreads();
    if (t == 0) {
        float A = 0.f, B = 0.f;
#pragma unroll
        for (int w = 0; w < 8; w++) { A += sh[w][0]; B += sh[w][1]; }
        const float inv = 1.f / ((float)NB * FSZ);
        float m   = A * inv;
        float E2  = B * inv;
        float var = E2 - m * m;
        float sc  = g1[r] * rsqrtf(var + EPSf);
        d_ss[(set * RN + r) * 2 + 0] = sc;
        d_ss[(set * RN + r) * 2 + 1] = b1[r] - m * sc;
    }
}

// ---------------- kernel 5: conv + BN1 + relu + channel-sum + softmax -------
// grid = (1024, 6), 384 threads (one output position per thread; 60 idle).
__global__ void __launch_bounds__(384) kmain(EPtrs ep, const float* __restrict__ E) {
    int set = blockIdx.y, b = blockIdx.x, t = threadIdx.x;
    __shared__ float img[EMB];
    __shared__ __align__(16) float rhs[RN * 12];   // [rh0..rh8, scale, shift, pad] per channel
    int eid = ep.e[set][b];
    float alpha = d_ab[set * 2 + 0], beta = d_ab[set * 2 + 1];

    for (int i = t; i < EMB; i += 384)
        img[i] = fmaf(E[(size_t)eid * EMB + i], alpha, beta);
    for (int i = t; i < RELF; i += 384) {
        int r = i / 9, k = i - r * 9;
        rhs[r * 12 + k] = d_rhat[(size_t)b * RELF + i];
    }
    if (t < RN) {
        rhs[t * 12 + 9]  = d_ss[(set * RN + t) * 2 + 0];
        rhs[t * 12 + 10] = d_ss[(set * RN + t) * 2 + 1];
        rhs[t * 12 + 11] = 0.f;
    }
    __syncthreads();

    float sacc = 0.f;
    int pos = t;
    bool act = pos < FSZ;
    if (act) {
        int y = pos / FHW, x = pos - y * FHW;
        float p0 = img[(y + 0) * WW + x + 0], p1 = img[(y + 0) * WW + x + 1], p2 = img[(y + 0) * WW + x + 2];
        float p3 = img[(y + 1) * WW + x + 0], p4 = img[(y + 1) * WW + x + 1], p5 = img[(y + 1) * WW + x + 2];
        float p6 = img[(y + 2) * WW + x + 0], p7 = img[(y + 2) * WW + x + 1], p8 = img[(y + 2) * WW + x + 2];
#pragma unroll 4
        for (int r = 0; r < RN; r++) {
            float4 a = *(const float4*)&rhs[r * 12 + 0];
            float4 c = *(const float4*)&rhs[r * 12 + 4];
            float4 d = *(const float4*)&rhs[r * 12 + 8];   // rh8, scale, shift, pad
            float v = p0 * a.x;
            v = fmaf(p1, a.y, v);  v = fmaf(p2, a.z, v);  v = fmaf(p3, a.w, v);
            v = fmaf(p4, c.x, v);  v = fmaf(p5, c.y, v);  v = fmaf(p6, c.z, v);
            v = fmaf(p7, c.w, v);  v = fmaf(p8, d.x, v);
            float yv = fmaf(v, d.y, d.z);
            sacc += fmaxf(yv, 0.f);
        }
    }

    // block softmax over pos < 324
    const float NEGINF = __int_as_float(0xff800000u);
    float mval = act ? sacc : NEGINF;
    float wm = warp_max(mval);
    __shared__ float sw[12];
    __shared__ float bm, bs;
    int wid = t >> 5, lane = t & 31;
    if (lane == 0) sw[wid] = wm;
    __syncthreads();
    if (t == 0) {
        float m = sw[0];
#pragma unroll
        for (int w = 1; w < 12; w++) m = fmaxf(m, sw[w]);
        bm = m;
    }
    __syncthreads();
    float ex = act ? __expf(sacc - bm) : 0.f;
    float wsum = warp_sum(ex);
    if (lane == 0) sw[wid] = wsum;
    __syncthreads();
    if (t == 0) {
        float s = 0.f;
#pragma unroll
        for (int w = 0; w < 12; w++) s += sw[w];
        bs = s;
    }
    __syncthreads();
    if (act) {
        float outv = (eid == 0) ? (1.f / (float)FSZ) : (ex / bs);
        d_soft[((size_t)set * NB + b) * FSZ + pos] = outv;
    }
}

// ---------------- kernel 6: 6-way product + dot with p ----------------------
// grid = 1024, 128 threads.
__global__ void kfinal(const float* __restrict__ p, float* __restrict__ out) {
    int b = blockIdx.x, t = threadIdx.x;
    float acc = 0.f;
    for (int pos = t; pos < FSZ; pos += 128) {
        float prod = d_soft[((size_t)0 * NB + b) * FSZ + pos];
#pragma unroll
        for (int s = 1; s < NSET; s++)
            prod *= d_soft[((size_t)s * NB + b) * FSZ + pos];
        acc = fmaf(prod, p[pos], acc);
    }
    float ws = warp_sum(acc);
    __shared__ float sw[4];
    if ((t & 31) == 0) sw[t >> 5] = ws;
    __syncthreads();
    if (t == 0) out[b] = sw[0] + sw[1] + sw[2] + sw[3];
}

// ---------------- launcher ---------------------------------------------------
extern "C" void kernel_launch(void* const* d_in, const int* in_sizes, int n_in,
                              void* d_out, int out_size) {
    const int*   r_idx = (const int*)d_in[0];
    EPtrs ep;
    for (int i = 0; i < NSET; i++) ep.e[i] = (const int*)d_in[1 + i];
    const float* E  = (const float*)d_in[7];
    const float* R  = (const float*)d_in[8];
    const float* g0 = (const float*)d_in[9];
    const float* b0 = (const float*)d_in[10];
    const float* g1 = (const float*)d_in[11];
    const float* b1 = (const float*)d_in[12];
    const float* g2 = (const float*)d_in[13];
    const float* b2 = (const float*)d_in[14];
    const float* p  = (const float*)d_in[15];
    float* out = (float*)d_out;

    krel    <<<RELF, 256>>>(r_idx, R, g2, b2);
    kstats1 <<<dim3(NB, NSET), 128>>>(ep, E);
    kreduce0<<<NSET, 256>>>(g0, b0);
    kstats2 <<<dim3(RN, NSET), 256>>>(g1, b1);
    kmain   <<<dim3(NB, NSET), 384>>>(ep, E);
    kfinal  <<<NB, 128>>>(p, out);
}

// round 3
// speedup vs baseline: 1.5135x; 1.5135x over previous
#include <cuda_runtime.h>
#include <math.h>

#define NB    1024
#define EMB   400
#define WW    20
#define FHW   18
#define FSZ   324
#define RN    96
#define RELF  864
#define NSET  6
#define NREL  500
#define EPSf  1e-5f

// ---------------- scratch ----------------------------------------------------
__device__ float d_rhat[(size_t)NB * RELF];
__device__ int   d_cnt[NREL];
__device__ float d_sc[RELF], d_sf[RELF];
__device__ float d_part[NSET * NB * 2];
__device__ float d_PQ[(size_t)NSET * NB * 54];
__device__ float d_ab[NSET * 2];
__device__ float d_p2[576 * 128 * 2];
__device__ float d_ss[NSET * RN * 2];
__device__ float d_soft[(size_t)NSET * NB * FSZ];

struct EPtrs { const int* e[NSET]; };

// ---------------- helpers ----------------------------------------------------
__device__ __forceinline__ float warp_sum(float v) {
#pragma unroll
    for (int o = 16; o > 0; o >>= 1) v += __shfl_down_sync(0xffffffffu, v, o);
    return v;
}
__device__ __forceinline__ float warp_max(float v) {
#pragma unroll
    for (int o = 16; o > 0; o >>= 1) v = fmaxf(v, __shfl_down_sync(0xffffffffu, v, o));
    return v;
}
__device__ __forceinline__ unsigned long long pk2(float lo, float hi) {
    unsigned long long r;
    asm("mov.b64 %0,{%1,%2};" : "=l"(r) : "f"(lo), "f"(hi));
    return r;
}
__device__ __forceinline__ void upk2(unsigned long long v, float& lo, float& hi) {
    asm("mov.b64 {%0,%1},%2;" : "=f"(lo), "=f"(hi) : "l"(v));
}
__device__ __forceinline__ unsigned long long mul2(unsigned long long a, unsigned long long b) {
    unsigned long long d;
    asm("mul.rn.f32x2 %0,%1,%2;" : "=l"(d) : "l"(a), "l"(b));
    return d;
}
__device__ __forceinline__ unsigned long long add2(unsigned long long a, unsigned long long b) {
    unsigned long long d;
    asm("add.rn.f32x2 %0,%1,%2;" : "=l"(d) : "l"(a), "l"(b));
    return d;
}
__device__ __forceinline__ unsigned long long fma2(unsigned long long a, unsigned long long b, unsigned long long c) {
    unsigned long long d;
    asm("fma.rn.f32x2 %0,%1,%2,%3;" : "=l"(d) : "l"(a), "l"(b), "l"(c));
    return d;
}

// ---------------- relation BN via histogram ----------------------------------
__global__ void khist(const int* __restrict__ r_idx) {
    __shared__ int h[NREL];
    int t = threadIdx.x;
    if (t < NREL) h[t] = 0;
    __syncthreads();
    atomicAdd(&h[r_idx[t]], 1);
    __syncthreads();
    if (t < NREL) d_cnt[t] = h[t];
}

__global__ void krstat(const float* __restrict__ R,
                       const float* __restrict__ g2, const float* __restrict__ b2) {
    __shared__ float cf[NREL];
    int t = threadIdx.x;
    for (int i = t; i < NREL; i += 128) cf[i] = (float)d_cnt[i];
    __syncthreads();
    int f = blockIdx.x * 128 + t;
    if (f >= RELF) return;
    float s = 0.f, s2 = 0.f;
    for (int rel = 0; rel < NREL; rel++) {
        float v = R[(size_t)rel * RELF + f];
        float c = cf[rel];
        s  = fmaf(c, v, s);
        s2 = fmaf(c * v, v, s2);
    }
    float m   = s * (1.f / NB);
    float var = s2 * (1.f / NB) - m * m;
    float sc  = rsqrtf(var + EPSf) * g2[f];
    d_sc[f] = sc;
    d_sf[f] = b2[f] - m * sc;
}

__global__ void kapply(const int* __restrict__ r_idx, const float* __restrict__ R) {
    int b = blockIdx.x, t = threadIdx.x;
    size_t base = (size_t)r_idx[b] * RELF;
    for (int i = t; i < RELF; i += 256)
        d_rhat[(size_t)b * RELF + i] = fmaf(R[base + i], d_sc[i], d_sf[i]);
}

// ---------------- kstats1: warp per (set,b) ----------------------------------
__global__ void __launch_bounds__(256) kstats1(EPtrs ep, const float* __restrict__ E) {
    int wid = threadIdx.x >> 5, lane = threadIdx.x & 31;
    int sid = blockIdx.x * 8 + wid;          // 0..6143
    int set = sid >> 10, b = sid & 1023;
    __shared__ float simg[8][400];
    int eid = ep.e[set][b];
    float s = 0.f, s2 = 0.f;
    for (int i = lane; i < EMB; i += 32) {
        float v = E[(size_t)eid * EMB + i];
        simg[wid][i] = v;
        s += v; s2 += v * v;
    }
    __syncwarp();
    s = warp_sum(s); s2 = warp_sum(s2);
    if (lane == 0) { d_part[sid * 2] = s; d_part[sid * 2 + 1] = s2; }

    float aP[9], aQ[45];
#pragma unroll
    for (int i = 0; i < 9; i++)  aP[i] = 0.f;
#pragma unroll
    for (int i = 0; i < 45; i++) aQ[i] = 0.f;
    const float* img = simg[wid];
    for (int pos = lane; pos < FSZ; pos += 32) {
        int y = pos / FHW, x = pos - y * FHW;
        float p[9];
#pragma unroll
        for (int dy = 0; dy < 3; dy++)
#pragma unroll
            for (int dx = 0; dx < 3; dx++)
                p[dy * 3 + dx] = img[(y + dy) * WW + (x + dx)];
        int q = 0;
#pragma unroll
        for (int k1 = 0; k1 < 9; k1++) {
            aP[k1] += p[k1];
#pragma unroll
            for (int k2 = k1; k2 < 9; k2++) { aQ[q] += p[k1] * p[k2]; q++; }
        }
    }
#pragma unroll
    for (int c = 0; c < 9; c++)  aP[c] = warp_sum(aP[c]);
#pragma unroll
    for (int c = 0; c < 45; c++) aQ[c] = warp_sum(aQ[c]);
    if (lane == 0) {
        size_t base = (size_t)sid * 54;
#pragma unroll
        for (int c = 0; c < 9; c++)  d_PQ[base + c] = aP[c];
#pragma unroll
        for (int c = 0; c < 45; c++) d_PQ[base + 9 + c] = aQ[c];
    }
}

// ---------------- kreduce0: BN0 alpha/beta -----------------------------------
__global__ void kreduce0(const float* __restrict__ g0, const float* __restrict__ b0) {
    int set = blockIdx.x, t = threadIdx.x;
    float s = 0.f, s2 = 0.f;
    for (int b = t; b < NB; b += 256) {
        s  += d_part[(set * NB + b) * 2 + 0];
        s2 += d_part[(set * NB + b) * 2 + 1];
    }
    float ws = warp_sum(s), ws2 = warp_sum(s2);
    __shared__ float sh[8][2];
    int wid = t >> 5, lane = t & 31;
    if (lane == 0) { sh[wid][0] = ws; sh[wid][1] = ws2; }
    __syncthreads();
    if (t == 0) {
        float S = 0.f, S2 = 0.f;
#pragma unroll
        for (int w = 0; w < 8; w++) { S += sh[w][0]; S2 += sh[w][1]; }
        const float inv = 1.f / ((float)NB * EMB);
        float m   = S * inv;
        float var = S2 * inv - m * m;
        float a   = g0[0] * rsqrtf(var + EPSf);
        d_ab[set * 2 + 0] = a;
        d_ab[set * 2 + 1] = b0[0] - m * a;
    }
}

// ---------------- kstats2a: b-major partials (smem reuse) --------------------
// grid = 128 blocks (8 samples each), 576 threads (one per set*96+r).
__global__ void __launch_bounds__(576) kstats2a() {
    __shared__ float s_rh[RELF];
    __shared__ float s_pq[NSET * 54];
    int t = threadIdx.x;
    int set = t / RN, r = t - set * RN;
    float alpha = d_ab[set * 2 + 0], beta = d_ab[set * 2 + 1];
    float S1 = 0.f, S2 = 0.f;
    for (int bi = 0; bi < 8; bi++) {
        int b = blockIdx.x * 8 + bi;
        __syncthreads();
        for (int i = t; i < RELF; i += 576) s_rh[i] = d_rhat[(size_t)b * RELF + i];
        for (int i = t; i < NSET * 54; i += 576) {
            int s_ = i / 54, j = i - s_ * 54;
            s_pq[i] = d_PQ[((size_t)s_ * NB + b) * 54 + j];
        }
        __syncthreads();
        const float* pq = &s_pq[set * 54];
        const float* rh = &s_rh[r * 9];
        float rhv[9], Srh = 0.f, SrP = 0.f;
#pragma unroll
        for (int k = 0; k < 9; k++) {
            rhv[k] = rh[k];
            Srh += rhv[k];
            SrP += rhv[k] * pq[k];
        }
        float quad = 0.f;
        int q = 0;
#pragma unroll
        for (int k1 = 0; k1 < 9; k1++) {
            quad += rhv[k1] * rhv[k1] * pq[9 + q]; q++;
#pragma unroll
            for (int k2 = k1 + 1; k2 < 9; k2++) {
                quad += 2.f * rhv[k1] * rhv[k2] * pq[9 + q]; q++;
            }
        }
        float mC = alpha * SrP + (float)FSZ * beta * Srh;
        float x2 = alpha * alpha * quad
                 + 2.f * alpha * beta * Srh * SrP
                 + (float)FSZ * beta * beta * Srh * Srh;
        S1 += mC;
        S2 += x2;
    }
    d_p2[(t * 128 + blockIdx.x) * 2 + 0] = S1;
    d_p2[(t * 128 + blockIdx.x) * 2 + 1] = S2;
}

// grid = 576 (one per set*96+r), 128 threads.
__global__ void kstats2b(const float* __restrict__ g1, const float* __restrict__ b1) {
    int c = blockIdx.x, t = threadIdx.x;
    int set = c / RN, r = c - set * RN;
    float v1 = d_p2[(c * 128 + t) * 2 + 0];
    float v2 = d_p2[(c * 128 + t) * 2 + 1];
    float w1 = warp_sum(v1), w2 = warp_sum(v2);
    __shared__ float sh[4][2];
    int wid = t >> 5, lane = t & 31;
    if (lane == 0) { sh[wid][0] = w1; sh[wid][1] = w2; }
    __syncthreads();
    if (t == 0) {
        float A = sh[0][0] + sh[1][0] + sh[2][0] + sh[3][0];
        float B = sh[0][1] + sh[1][1] + sh[2][1] + sh[3][1];
        const float inv = 1.f / ((float)NB * FSZ);
        float m   = A * inv;
        float var = B * inv - m * m;
        float sc  = g1[r] * rsqrtf(var + EPSf);
        d_ss[(set * RN + r) * 2 + 0] = sc;
        d_ss[(set * RN + r) * 2 + 1] = b1[r] - m * sc;
    }
}

// ---------------- kmain: packed f32x2 conv + BN1 + relu-sum + softmax --------
// grid = (1024, 6), 96 threads; threads 0..80 each own 4 positions (2 f32x2 pairs).
#define TKM 96
__global__ void __launch_bounds__(TKM) kmain(EPtrs ep, const float* __restrict__ E) {
    int set = blockIdx.y, b = blockIdx.x, t = threadIdx.x;
    __shared__ float img[EMB];
    __shared__ __align__(16) float2 rw[RN * 12];   // {w,w} pairs: k0..k8, scale, shift, pad
    int eid = ep.e[set][b];
    float alpha = d_ab[set * 2 + 0], beta = d_ab[set * 2 + 1];

    for (int i = t; i < EMB; i += TKM)
        img[i] = fmaf(E[(size_t)eid * EMB + i], alpha, beta);
#pragma unroll
    for (int it = 0; it < 9; it++) {
        int i = t + it * TKM;                       // covers 0..863
        int r = i / 9, k = i - r * 9;
        float w = d_rhat[(size_t)b * RELF + i];
        rw[r * 12 + k] = make_float2(w, w);
    }
    {
        float sc = d_ss[(set * RN + t) * 2 + 0];
        float sh = d_ss[(set * RN + t) * 2 + 1];
        rw[t * 12 + 9]  = make_float2(sc, sc);
        rw[t * 12 + 10] = make_float2(sh, sh);
        rw[t * 12 + 11] = make_float2(0.f, 0.f);
    }
    __syncthreads();

    bool act = t < 81;
    unsigned long long pA[9], pB[9];
    if (act) {
        float pv[4][9];
#pragma unroll
        for (int j = 0; j < 4; j++) {
            int pos = 4 * t + j;
            int y = pos / FHW, x = pos - y * FHW;
#pragma unroll
            for (int dy = 0; dy < 3; dy++)
#pragma unroll
                for (int dx = 0; dx < 3; dx++)
                    pv[j][dy * 3 + dx] = img[(y + dy) * WW + (x + dx)];
        }
#pragma unroll
        for (int k = 0; k < 9; k++) {
            pA[k] = pk2(pv[0][k], pv[1][k]);
            pB[k] = pk2(pv[2][k], pv[3][k]);
        }
    } else {
#pragma unroll
        for (int k = 0; k < 9; k++) { pA[k] = 0ull; pB[k] = 0ull; }
    }

    const unsigned long long ABSM = 0x7fffffff7fffffffULL;
    unsigned long long sA = 0ull, sB = 0ull;       // packed sum of (y + |y|)
    const ulonglong2* rwq = (const ulonglong2*)rw;
#pragma unroll 2
    for (int r = 0; r < RN; r++) {
        ulonglong2 q0 = rwq[r * 6 + 0];            // k0,k1
        ulonglong2 q1 = rwq[r * 6 + 1];            // k2,k3
        ulonglong2 q2 = rwq[r * 6 + 2];            // k4,k5
        ulonglong2 q3 = rwq[r * 6 + 3];            // k6,k7
        ulonglong2 q4 = rwq[r * 6 + 4];            // k8,scale
        ulonglong2 q5 = rwq[r * 6 + 5];            // shift,pad
        unsigned long long a = mul2(pA[0], q0.x);
        a = fma2(pA[1], q0.y, a);  a = fma2(pA[2], q1.x, a);
        a = fma2(pA[3], q1.y, a);  a = fma2(pA[4], q2.x, a);
        a = fma2(pA[5], q2.y, a);  a = fma2(pA[6], q3.x, a);
        a = fma2(pA[7], q3.y, a);  a = fma2(pA[8], q4.x, a);
        a = fma2(a, q4.y, q5.x);                   // BN1 scale/shift
        sA = add2(sA, add2(a, a & ABSM));          // += y + |y| = 2*relu(y)

        unsigned long long c = mul2(pB[0], q0.x);
        c = fma2(pB[1], q0.y, c);  c = fma2(pB[2], q1.x, c);
        c = fma2(pB[3], q1.y, c);  c = fma2(pB[4], q2.x, c);
        c = fma2(pB[5], q2.y, c);  c = fma2(pB[6], q3.x, c);
        c = fma2(pB[7], q3.y, c);  c = fma2(pB[8], q4.x, c);
        c = fma2(c, q4.y, q5.x);
        sB = add2(sB, add2(c, c & ABSM));
    }
    float v0, v1, v2, v3;
    upk2(sA, v0, v1); upk2(sB, v2, v3);
    v0 *= 0.5f; v1 *= 0.5f; v2 *= 0.5f; v3 *= 0.5f;

    // block softmax over 324 positions (4 per active thread, 3 warps)
    const float NEGINF = __int_as_float(0xff800000u);
    float lm = act ? fmaxf(fmaxf(v0, v1), fmaxf(v2, v3)) : NEGINF;
    float wm = warp_max(lm);
    __shared__ float swr[3];
    __shared__ float sbm, sbs;
    int wid = t >> 5, lane = t & 31;
    if (lane == 0) swr[wid] = wm;
    __syncthreads();
    if (t == 0) sbm = fmaxf(fmaxf(swr[0], swr[1]), swr[2]);
    __syncthreads();
    float bm = sbm;
    float e0 = 0.f, e1 = 0.f, e2 = 0.f, e3 = 0.f;
    if (act) {
        e0 = __expf(v0 - bm); e1 = __expf(v1 - bm);
        e2 = __expf(v2 - bm); e3 = __expf(v3 - bm);
    }
    float ls = (e0 + e1) + (e2 + e3);
    float ws = warp_sum(ls);
    if (lane == 0) swr[wid] = ws;
    __syncthreads();
    if (t == 0) sbs = swr[0] + swr[1] + swr[2];
    __syncthreads();
    if (act) {
        float4 o;
        if (eid == 0) {
            float u = 1.f / (float)FSZ;
            o = make_float4(u, u, u, u);
        } else {
            float inv = 1.f / sbs;
            o = make_float4(e0 * inv, e1 * inv, e2 * inv, e3 * inv);
        }
        *(float4*)&d_soft[((size_t)set * NB + b) * FSZ + 4 * t] = o;
    }
}

// ---------------- kfinal -----------------------------------------------------
__global__ void kfinal(const float* __restrict__ p, float* __restrict__ out) {
    int b = blockIdx.x, t = threadIdx.x;
    float acc = 0.f;
    for (int pos = t; pos < FSZ; pos += 128) {
        float prod = d_soft[((size_t)0 * NB + b) * FSZ + pos];
#pragma unroll
        for (int s = 1; s < NSET; s++)
            prod *= d_soft[((size_t)s * NB + b) * FSZ + pos];
        acc = fmaf(prod, p[pos], acc);
    }
    float ws = warp_sum(acc);
    __shared__ float sw[4];
    if ((t & 31) == 0) sw[t >> 5] = ws;
    __syncthreads();
    if (t == 0) out[b] = sw[0] + sw[1] + sw[2] + sw[3];
}

// ---------------- launcher ---------------------------------------------------
extern "C" void kernel_launch(void* const* d_in, const int* in_sizes, int n_in,
                              void* d_out, int out_size) {
    const int* r_idx = (const int*)d_in[0];
    EPtrs ep;
    for (int i = 0; i < NSET; i++) ep.e[i] = (const int*)d_in[1 + i];
    const float* E  = (const float*)d_in[7];
    const float* R  = (const float*)d_in[8];
    const float* g0 = (const float*)d_in[9];
    const float* b0 = (const float*)d_in[10];
    const float* g1 = (const float*)d_in[11];
    const float* b1 = (const float*)d_in[12];
    const float* g2 = (const float*)d_in[13];
    const float* b2 = (const float*)d_in[14];
    const float* p  = (const float*)d_in[15];
    float* out = (float*)d_out;

    khist   <<<1, NB>>>(r_idx);
    krstat  <<<7, 128>>>(R, g2, b2);
    kapply  <<<NB, 256>>>(r_idx, R);
    kstats1 <<<768, 256>>>(ep, E);
    kreduce0<<<NSET, 256>>>(g0, b0);
    kstats2a<<<128, 576>>>();
    kstats2b<<<576, 128>>>(g1, b1);
    kmain   <<<dim3(NB, NSET), TKM>>>(ep, E);
    kfinal  <<<NB, 128>>>(p, out);
}

// round 4
// speedup vs baseline: 1.6798x; 1.1098x over previous
#include <cuda_runtime.h>
#include <math.h>

#define NB    1024
#define EMB   400
#define WW    20
#define FHW   18
#define FSZ   324
#define RN    96
#define RELF  864
#define NSET  6
#define NREL  500
#define EPSf  1e-5f

// ---------------- scratch ----------------------------------------------------
__device__ float d_rhat[(size_t)NB * RELF];
__device__ int   d_cnt[NREL];
__device__ float d_sc[RELF], d_sf[RELF];
__device__ float d_part[NSET * NB * 2];
__device__ float d_PQ[(size_t)NSET * NB * 54];
__device__ float d_ab[NSET * 2];
__device__ float d_p2[576 * 128 * 2];
__device__ float d_ss[NSET * RN * 2];
__device__ float d_soft[(size_t)NSET * NB * FSZ];

struct EPtrs { const int* e[NSET]; };

// ---------------- helpers ----------------------------------------------------
__device__ __forceinline__ float warp_sum(float v) {
#pragma unroll
    for (int o = 16; o > 0; o >>= 1) v += __shfl_down_sync(0xffffffffu, v, o);
    return v;
}
__device__ __forceinline__ float hsum16(float v) {
#pragma unroll
    for (int o = 8; o > 0; o >>= 1) v += __shfl_down_sync(0xffffffffu, v, o, 16);
    return v;
}
__device__ __forceinline__ unsigned long long pk2(float lo, float hi) {
    unsigned long long r;
    asm("mov.b64 %0,{%1,%2};" : "=l"(r) : "f"(lo), "f"(hi));
    return r;
}
__device__ __forceinline__ void upk2(unsigned long long v, float& lo, float& hi) {
    asm("mov.b64 {%0,%1},%2;" : "=f"(lo), "=f"(hi) : "l"(v));
}
__device__ __forceinline__ unsigned long long add2(unsigned long long a, unsigned long long b) {
    unsigned long long d;
    asm("add.rn.f32x2 %0,%1,%2;" : "=l"(d) : "l"(a), "l"(b));
    return d;
}
__device__ __forceinline__ unsigned long long fma2(unsigned long long a, unsigned long long b, unsigned long long c) {
    unsigned long long d;
    asm("fma.rn.f32x2 %0,%1,%2,%3;" : "=l"(d) : "l"(a), "l"(b), "l"(c));
    return d;
}

// ---------------- relation BN via histogram ----------------------------------
__global__ void khist(const int* __restrict__ r_idx) {
    __shared__ int h[NREL];
    int t = threadIdx.x;
    if (t < NREL) h[t] = 0;
    __syncthreads();
    atomicAdd(&h[r_idx[t]], 1);
    __syncthreads();
    if (t < NREL) d_cnt[t] = h[t];
}

__global__ void krstat(const float* __restrict__ R,
                       const float* __restrict__ g2, const float* __restrict__ b2) {
    __shared__ float cf[NREL];
    int t = threadIdx.x;
    for (int i = t; i < NREL; i += 128) cf[i] = (float)d_cnt[i];
    __syncthreads();
    int f = blockIdx.x * 128 + t;
    if (f >= RELF) return;
    float s = 0.f, s2 = 0.f;
    for (int rel = 0; rel < NREL; rel++) {
        float v = R[(size_t)rel * RELF + f];
        float c = cf[rel];
        s  = fmaf(c, v, s);
        s2 = fmaf(c * v, v, s2);
    }
    float m   = s * (1.f / NB);
    float var = s2 * (1.f / NB) - m * m;
    float sc  = rsqrtf(var + EPSf) * g2[f];
    d_sc[f] = sc;
    d_sf[f] = b2[f] - m * sc;
}

__global__ void kapply(const int* __restrict__ r_idx, const float* __restrict__ R) {
    int b = blockIdx.x, t = threadIdx.x;
    size_t base = (size_t)r_idx[b] * RELF;
    for (int i = t; i < RELF; i += 256)
        d_rhat[(size_t)b * RELF + i] = fmaf(R[base + i], d_sc[i], d_sf[i]);
}

// ---------------- kstats1: 16 lanes per sample, 2 samples/warp ---------------
// grid = 384 blocks, 256 threads; block = 16 samples.
__global__ void __launch_bounds__(256) kstats1(EPtrs ep, const float* __restrict__ E) {
    int t = threadIdx.x;
    int wid = t >> 5, lane = t & 31;
    int g = lane >> 4, l16 = lane & 15;
    __shared__ float simg[16][400];
    int sid0 = blockIdx.x * 16 + wid * 2;

    // warp cooperatively loads its 2 samples; accumulates sum/sumsq on the fly
#pragma unroll
    for (int ss = 0; ss < 2; ss++) {
        int sid2 = sid0 + ss;
        int set2 = sid2 >> 10, b2 = sid2 & 1023;
        int eid2 = ep.e[set2][b2];
        float s = 0.f, s2 = 0.f;
        for (int i = lane; i < EMB; i += 32) {
            float v = E[(size_t)eid2 * EMB + i];
            simg[wid * 2 + ss][i] = v;
            s += v; s2 += v * v;
        }
        s = warp_sum(s); s2 = warp_sum(s2);
        if (lane == 0) { d_part[sid2 * 2] = s; d_part[sid2 * 2 + 1] = s2; }
    }
    __syncwarp();

    int sid = sid0 + g;
    const float* img = simg[wid * 2 + g];
    float aP[9], aQ[45];
#pragma unroll
    for (int i = 0; i < 9; i++)  aP[i] = 0.f;
#pragma unroll
    for (int i = 0; i < 45; i++) aQ[i] = 0.f;

    int pos = l16, y = 0, x = l16;
    while (pos < FSZ) {
        const float* row0 = &img[y * WW + x];
        float p[9];
#pragma unroll
        for (int dy = 0; dy < 3; dy++)
#pragma unroll
            for (int dx = 0; dx < 3; dx++)
                p[dy * 3 + dx] = row0[dy * WW + dx];
        int q = 0;
#pragma unroll
        for (int k1 = 0; k1 < 9; k1++) {
            aP[k1] += p[k1];
#pragma unroll
            for (int k2 = k1; k2 < 9; k2++) { aQ[q] = fmaf(p[k1], p[k2], aQ[q]); q++; }
        }
        pos += 16; x += 16;
        if (x >= FHW) { x -= FHW; y += 1; }
    }
#pragma unroll
    for (int c = 0; c < 9; c++)  aP[c] = hsum16(aP[c]);
#pragma unroll
    for (int c = 0; c < 45; c++) aQ[c] = hsum16(aQ[c]);
    if (l16 == 0) {
        size_t base = (size_t)sid * 54;
#pragma unroll
        for (int c = 0; c < 9; c++)  d_PQ[base + c] = aP[c];
#pragma unroll
        for (int c = 0; c < 45; c++) d_PQ[base + 9 + c] = aQ[c];
    }
}

// ---------------- kreduce0: BN0 alpha/beta -----------------------------------
__global__ void kreduce0(const float* __restrict__ g0, const float* __restrict__ b0) {
    int set = blockIdx.x, t = threadIdx.x;
    float s = 0.f, s2 = 0.f;
    for (int b = t; b < NB; b += 256) {
        s  += d_part[(set * NB + b) * 2 + 0];
        s2 += d_part[(set * NB + b) * 2 + 1];
    }
    float ws = warp_sum(s), ws2 = warp_sum(s2);
    __shared__ float sh[8][2];
    int wid = t >> 5, lane = t & 31;
    if (lane == 0) { sh[wid][0] = ws; sh[wid][1] = ws2; }
    __syncthreads();
    if (t == 0) {
        float S = 0.f, S2 = 0.f;
#pragma unroll
        for (int w = 0; w < 8; w++) { S += sh[w][0]; S2 += sh[w][1]; }
        const float inv = 1.f / ((float)NB * EMB);
        float m   = S * inv;
        float var = S2 * inv - m * m;
        float a   = g0[0] * rsqrtf(var + EPSf);
        d_ab[set * 2 + 0] = a;
        d_ab[set * 2 + 1] = b0[0] - m * a;
    }
}

// ---------------- kstats2a: b-major partials (smem reuse) --------------------
__global__ void __launch_bounds__(576) kstats2a() {
    __shared__ float s_rh[RELF];
    __shared__ float s_pq[NSET * 54];
    int t = threadIdx.x;
    int set = t / RN, r = t - set * RN;
    float alpha = d_ab[set * 2 + 0], beta = d_ab[set * 2 + 1];
    float S1 = 0.f, S2 = 0.f;
    for (int bi = 0; bi < 8; bi++) {
        int b = blockIdx.x * 8 + bi;
        __syncthreads();
        for (int i = t; i < RELF; i += 576) s_rh[i] = d_rhat[(size_t)b * RELF + i];
        for (int i = t; i < NSET * 54; i += 576) {
            int s_ = i / 54, j = i - s_ * 54;
            s_pq[i] = d_PQ[((size_t)s_ * NB + b) * 54 + j];
        }
        __syncthreads();
        const float* pq = &s_pq[set * 54];
        const float* rh = &s_rh[r * 9];
        float rhv[9], Srh = 0.f, SrP = 0.f;
#pragma unroll
        for (int k = 0; k < 9; k++) {
            rhv[k] = rh[k];
            Srh += rhv[k];
            SrP += rhv[k] * pq[k];
        }
        float quad = 0.f;
        int q = 0;
#pragma unroll
        for (int k1 = 0; k1 < 9; k1++) {
            quad += rhv[k1] * rhv[k1] * pq[9 + q]; q++;
#pragma unroll
            for (int k2 = k1 + 1; k2 < 9; k2++) {
                quad += 2.f * rhv[k1] * rhv[k2] * pq[9 + q]; q++;
            }
        }
        float mC = alpha * SrP + (float)FSZ * beta * Srh;
        float x2 = alpha * alpha * quad
                 + 2.f * alpha * beta * Srh * SrP
                 + (float)FSZ * beta * beta * Srh * Srh;
        S1 += mC;
        S2 += x2;
    }
    d_p2[(t * 128 + blockIdx.x) * 2 + 0] = S1;
    d_p2[(t * 128 + blockIdx.x) * 2 + 1] = S2;
}

__global__ void kstats2b(const float* __restrict__ g1, const float* __restrict__ b1) {
    int c = blockIdx.x, t = threadIdx.x;
    int set = c / RN, r = c - set * RN;
    float v1 = d_p2[(c * 128 + t) * 2 + 0];
    float v2 = d_p2[(c * 128 + t) * 2 + 1];
    float w1 = warp_sum(v1), w2 = warp_sum(v2);
    __shared__ float sh[4][2];
    int wid = t >> 5, lane = t & 31;
    if (lane == 0) { sh[wid][0] = w1; sh[wid][1] = w2; }
    __syncthreads();
    if (t == 0) {
        float A = sh[0][0] + sh[1][0] + sh[2][0] + sh[3][0];
        float B = sh[0][1] + sh[1][1] + sh[2][1] + sh[3][1];
        const float inv = 1.f / ((float)NB * FSZ);
        float m   = A * inv;
        float var = B * inv - m * m;
        float sc  = g1[r] * rsqrtf(var + EPSf);
        d_ss[(set * RN + r) * 2 + 0] = sc;
        d_ss[(set * RN + r) * 2 + 1] = b1[r] - m * sc;
    }
}

// ---------------- kmain v3 ---------------------------------------------------
// grid = (1024, 6), 128 threads = 4 warps; warp w handles channels [24w, 24w+24),
// each lane holds 12 consecutive positions as 54 packed f32x2 registers.
#define TKM 128
__global__ void __launch_bounds__(TKM) kmain(EPtrs ep, const float* __restrict__ E) {
    int set = blockIdx.y, b = blockIdx.x, t = threadIdx.x;
    int wid = t >> 5, lane = t & 31;
    __shared__ float img[EMB];
    __shared__ __align__(16) float2 rw[RN * 10];    // per ch: 9 {sc*w} pairs + {sh} pair
    __shared__ float ssc[RN];
    __shared__ __align__(16) float2 red[4][32][6];

    int eid = ep.e[set][b];
    float alpha = d_ab[set * 2 + 0], beta = d_ab[set * 2 + 1];

    // phase A: raw weights to regs, scale/shift to smem/regs, normalized image
    float vreg[7];
#pragma unroll
    for (int j = 0; j < 7; j++) {
        int i = t + j * TKM;
        vreg[j] = (i < RELF) ? d_rhat[(size_t)b * RELF + i] : 0.f;
    }
    float mysh = 0.f;
    if (t < RN) {
        ssc[t] = d_ss[(set * RN + t) * 2 + 0];
        mysh   = d_ss[(set * RN + t) * 2 + 1];
    }
    for (int i = t; i < EMB; i += TKM)
        img[i] = fmaf(E[(size_t)eid * EMB + i], alpha, beta);
    __syncthreads();

    // phase B: scale-folded duplicated weight pairs
#pragma unroll
    for (int j = 0; j < 7; j++) {
        int i = t + j * TKM;
        if (i < RELF) {
            int r = i / 9, k = i - r * 9;
            float w = vreg[j] * ssc[r];
            rw[r * 10 + k] = make_float2(w, w);
        }
    }
    if (t < RN) rw[t * 10 + 9] = make_float2(mysh, mysh);
    __syncthreads();

    // phase C: 12 consecutive positions per lane into packed registers
    int l = (lane < 27) ? lane : 26;
    unsigned long long P[6][9];
    {
        int base = 12 * l;
#pragma unroll
        for (int j = 0; j < 6; j++) {
            int p0 = base + 2 * j, p1 = p0 + 1;
            int y0 = p0 / FHW, x0 = p0 - y0 * FHW;
            int y1 = p1 / FHW, x1 = p1 - y1 * FHW;
#pragma unroll
            for (int dy = 0; dy < 3; dy++)
#pragma unroll
                for (int dx = 0; dx < 3; dx++)
                    P[j][dy * 3 + dx] = pk2(img[(y0 + dy) * WW + x0 + dx],
                                            img[(y1 + dy) * WW + x1 + dx]);
        }
    }

    const unsigned long long ABSM = 0x7fffffff7fffffffULL;
    unsigned long long S[6];
#pragma unroll
    for (int j = 0; j < 6; j++) S[j] = 0ull;
    const ulonglong2* rwq = (const ulonglong2*)rw;  // 5 x 16B per channel
    int r0 = wid * 24;
#pragma unroll 2
    for (int rr = 0; rr < 24; rr++) {
        int r = r0 + rr;
        ulonglong2 q0 = rwq[r * 5 + 0];
        ulonglong2 q1 = rwq[r * 5 + 1];
        ulonglong2 q2 = rwq[r * 5 + 2];
        ulonglong2 q3 = rwq[r * 5 + 3];
        ulonglong2 q4 = rwq[r * 5 + 4];   // w8, shift
#pragma unroll
        for (int j = 0; j < 6; j++) {
            unsigned long long a = fma2(P[j][0], q0.x, q4.y);
            a = fma2(P[j][1], q0.y, a);  a = fma2(P[j][2], q1.x, a);
            a = fma2(P[j][3], q1.y, a);  a = fma2(P[j][4], q2.x, a);
            a = fma2(P[j][5], q2.y, a);  a = fma2(P[j][6], q3.x, a);
            a = fma2(P[j][7], q3.y, a);  a = fma2(P[j][8], q4.x, a);
            S[j] = add2(S[j], add2(a, a & ABSM));   // += y + |y| = 2*relu(y)
        }
    }
#pragma unroll
    for (int j = 0; j < 6; j++) {
        float lo, hi; upk2(S[j], lo, hi);
        red[wid][lane][j] = make_float2(lo, hi);
    }
    __syncthreads();

    if (wid == 0) {
        float v[12];
#pragma unroll
        for (int j = 0; j < 6; j++) {
            float2 a0 = red[0][lane][j], a1 = red[1][lane][j];
            float2 a2 = red[2][lane][j], a3 = red[3][lane][j];
            v[2 * j]     = 0.5f * ((a0.x + a1.x) + (a2.x + a3.x));
            v[2 * j + 1] = 0.5f * ((a0.y + a1.y) + (a2.y + a3.y));
        }
        bool act = lane < 27;
        const float NEGINF = __int_as_float(0xff800000u);
        float lm = NEGINF;
        if (act) {
#pragma unroll
            for (int j = 0; j < 12; j++) lm = fmaxf(lm, v[j]);
        }
#pragma unroll
        for (int o = 16; o > 0; o >>= 1)
            lm = fmaxf(lm, __shfl_xor_sync(0xffffffffu, lm, o));
        float e[12], ls = 0.f;
        if (act) {
#pragma unroll
            for (int j = 0; j < 12; j++) { e[j] = __expf(v[j] - lm); ls += e[j]; }
        }
#pragma unroll
        for (int o = 16; o > 0; o >>= 1)
            ls += __shfl_xor_sync(0xffffffffu, ls, o);
        if (act) {
            float* dst = &d_soft[((size_t)set * NB + b) * FSZ + 12 * lane];
            if (eid == 0) {
                const float u = 1.f / (float)FSZ;
#pragma unroll
                for (int j = 0; j < 3; j++)
                    *(float4*)&dst[4 * j] = make_float4(u, u, u, u);
            } else {
                float inv = 1.f / ls;
#pragma unroll
                for (int j = 0; j < 3; j++)
                    *(float4*)&dst[4 * j] = make_float4(e[4*j] * inv, e[4*j+1] * inv,
                                                        e[4*j+2] * inv, e[4*j+3] * inv);
            }
        }
    }
}

// ---------------- kfinal -----------------------------------------------------
__global__ void kfinal(const float* __restrict__ p, float* __restrict__ out) {
    int b = blockIdx.x, t = threadIdx.x;
    float acc = 0.f;
    for (int pos = t; pos < FSZ; pos += 128) {
        float prod = d_soft[((size_t)0 * NB + b) * FSZ + pos];
#pragma unroll
        for (int s = 1; s < NSET; s++)
            prod *= d_soft[((size_t)s * NB + b) * FSZ + pos];
        acc = fmaf(prod, p[pos], acc);
    }
    float ws = warp_sum(acc);
    __shared__ float sw[4];
    if ((t & 31) == 0) sw[t >> 5] = ws;
    __syncthreads();
    if (t == 0) out[b] = sw[0] + sw[1] + sw[2] + sw[3];
}

// ---------------- launcher ---------------------------------------------------
extern "C" void kernel_launch(void* const* d_in, const int* in_sizes, int n_in,
                              void* d_out, int out_size) {
    const int* r_idx = (const int*)d_in[0];
    EPtrs ep;
    for (int i = 0; i < NSET; i++) ep.e[i] = (const int*)d_in[1 + i];
    const float* E  = (const float*)d_in[7];
    const float* R  = (const float*)d_in[8];
    const float* g0 = (const float*)d_in[9];
    const float* b0 = (const float*)d_in[10];
    const float* g1 = (const float*)d_in[11];
    const float* b1 = (const float*)d_in[12];
    const float* g2 = (const float*)d_in[13];
    const float* b2 = (const float*)d_in[14];
    const float* p  = (const float*)d_in[15];
    float* out = (float*)d_out;

    khist   <<<1, NB>>>(r_idx);
    krstat  <<<7, 128>>>(R, g2, b2);
    kapply  <<<NB, 256>>>(r_idx, R);
    kstats1 <<<384, 256>>>(ep, E);
    kreduce0<<<NSET, 256>>>(g0, b0);
    kstats2a<<<128, 576>>>();
    kstats2b<<<576, 128>>>(g1, b1);
    kmain   <<<dim3(NB, NSET), TKM>>>(ep, E);
    kfinal  <<<NB, 128>>>(p, out);
}